// round 3
// baseline (speedup 1.0000x reference)
#include <cuda_runtime.h>

// Problem constants
#define NPOS 2304          // 48*48
#define PPAD 2916          // 54*54

// Scratch (device globals; no runtime allocation)
__device__ float Qbuf[2 * 4 * 2304 * 64];   // [b][g][p][c64]
__device__ float Kbuf[2 * 8 * 2916 * 32];   // [b][SL][padded pos][c32]
__device__ float Vbuf[2 * 4 * 2916 * 64];   // [b][g][padded pos][c64]

// ---------------------------------------------------------------------------
// Kernel 0: zero only the 612 border positions of each K/V plane (2.5 MB)
// ---------------------------------------------------------------------------
__device__ __forceinline__ int border_pp(int idx) {
    // idx in [0,612) -> padded position in 54x54 grid outside interior [3,51)x[3,51)
    if (idx < 162) { int r = idx / 54, c = idx % 54; return r * 54 + c; }
    if (idx < 324) { int k = idx - 162; int r = 51 + k / 54, c = k % 54; return r * 54 + c; }
    int k = idx - 324;
    int r = 3 + k / 6;
    int cc = k % 6;
    int c = (cc < 3) ? cc : (cc + 48);
    return r * 54 + c;
}

__global__ void zero_border_kernel() {
    const int NB = 612;
    const int KITEMS = 16 * NB;   // (b,SL) planes
    const int VITEMS = 8 * NB;    // (b,g) planes
    int t = blockIdx.x * blockDim.x + threadIdx.x;
    float4 z = make_float4(0.f, 0.f, 0.f, 0.f);
    if (t < KITEMS) {
        int plane = t / NB, idx = t % NB;
        int pp = border_pp(idx);
        float4* p = (float4*)(Kbuf + ((plane * PPAD + pp) << 5));
#pragma unroll
        for (int i = 0; i < 8; i++) p[i] = z;
    } else if (t < KITEMS + VITEMS) {
        int tt = t - KITEMS;
        int plane = tt / NB, idx = tt % NB;
        int pp = border_pp(idx);
        float4* p = (float4*)(Vbuf + ((plane * PPAD + pp) << 6));
#pragma unroll
        for (int i = 0; i < 16; i++) p[i] = z;
    }
}

// ---------------------------------------------------------------------------
// Kernel 1: 1x1 conv GEMM with packed f32x2 FMA (FFMA2).
// C[768,2304] = W[768,256] * X[256,2304] per batch.
// 128(o) x 128(n) tile, 256 threads (16x16), 8x8 microtile, n packed in pairs.
// ---------------------------------------------------------------------------
__device__ __forceinline__ unsigned long long dup2(float a) {
    unsigned long long r;
    asm("mov.b64 %0, {%1, %1};" : "=l"(r) : "f"(a));
    return r;
}
__device__ __forceinline__ void fma2(unsigned long long& d, unsigned long long a,
                                     unsigned long long b) {
    asm("fma.rn.f32x2 %0, %1, %2, %0;" : "+l"(d) : "l"(a), "l"(b));
}

__global__ __launch_bounds__(256, 2) void conv_kernel(const float* __restrict__ x,
                                                      const float* __restrict__ w) {
    __shared__ float As[16][128];   // [k][o]
    __shared__ float Bs[16][128];   // [k][n]
    __shared__ float Cs[8][132];    // epilogue transpose buffer [n8][o]

    const int b  = blockIdx.z;
    const int o0 = blockIdx.y * 128;
    const int n0 = blockIdx.x * 128;
    const int t  = threadIdx.x;
    const int tx = t & 15;      // n (x8)
    const int ty = t >> 4;      // o (x8)

    const float* Xb = x + b * (256 * NPOS);

    unsigned long long acc[8][4];
#pragma unroll
    for (int i = 0; i < 8; i++)
#pragma unroll
        for (int j = 0; j < 4; j++) acc[i][j] = 0ull;

    // A loader: 512 float4 per k-step; fid = t + rep*256; o = fid>>2, kq = fid&3
    // B loader: fid = t + rep*256; kk = fid>>5, nf4 = fid&31
    for (int c0 = 0; c0 < 256; c0 += 16) {
        float4 av[2], bv[2];
#pragma unroll
        for (int rep = 0; rep < 2; rep++) {
            int fid = t + rep * 256;
            int ao = fid >> 2, akq = fid & 3;
            av[rep] = *(const float4*)(w + (o0 + ao) * 256 + c0 + akq * 4);
            int bkk = fid >> 5, bn4 = fid & 31;
            bv[rep] = *(const float4*)(Xb + (c0 + bkk) * NPOS + n0 + bn4 * 4);
        }
        __syncthreads();
#pragma unroll
        for (int rep = 0; rep < 2; rep++) {
            int fid = t + rep * 256;
            int ao = fid >> 2, akq = fid & 3;
            As[akq * 4 + 0][ao] = av[rep].x;
            As[akq * 4 + 1][ao] = av[rep].y;
            As[akq * 4 + 2][ao] = av[rep].z;
            As[akq * 4 + 3][ao] = av[rep].w;
            int bkk = fid >> 5, bn4 = fid & 31;
            *(float4*)&Bs[bkk][bn4 * 4] = bv[rep];
        }
        __syncthreads();
#pragma unroll
        for (int kk = 0; kk < 16; kk++) {
            unsigned long long bp[4];
            *(float4*)&bp[0] = *(const float4*)&Bs[kk][tx * 8];
            *(float4*)&bp[2] = *(const float4*)&Bs[kk][tx * 8 + 4];
            float a[8];
            *(float4*)&a[0] = *(const float4*)&As[kk][ty * 8];
            *(float4*)&a[4] = *(const float4*)&As[kk][ty * 8 + 4];
#pragma unroll
            for (int i = 0; i < 8; i++) {
                unsigned long long A2 = dup2(a[i]);
                fma2(acc[i][0], A2, bp[0]);
                fma2(acc[i][1], A2, bp[1]);
                fma2(acc[i][2], A2, bp[2]);
                fma2(acc[i][3], A2, bp[3]);
            }
        }
    }

    // Epilogue: 16 rounds; round r transposes n-subblock [8r, 8r+8) through smem
    // and stores coalesced float4 runs into Q/K/V layouts.
#pragma unroll 1
    for (int r = 0; r < 16; r++) {
        __syncthreads();
        if (tx == r) {
#pragma unroll
            for (int i = 0; i < 8; i++)
#pragma unroll
                for (int j = 0; j < 4; j++) {
                    float2 v = *(float2*)&acc[i][j];
                    Cs[2 * j + 0][ty * 8 + i] = v.x;
                    Cs[2 * j + 1][ty * 8 + i] = v.y;
                }
        }
        __syncthreads();
        {
            int row = t >> 5;           // n offset 0..7
            int of4 = t & 31;           // o float4 index 0..31
            float4 v = *(const float4*)&Cs[row][of4 * 4];
            int hw = n0 + r * 8 + row;
            int o  = o0 + of4 * 4;
            int i2 = hw / 48, j2 = hw % 48;
            int pp = (i2 + 3) * 54 + (j2 + 3);
            if (o < 256) {
                int g = o >> 6;
                *(float4*)&Qbuf[(((b * 4 + g) * 2304 + hw) << 6) + (o & 63)] = v;
            } else if (o < 512) {
                int ok = o - 256;
                int SL = ((ok >> 5) & 1) * 4 + (ok >> 6);
                *(float4*)&Kbuf[(((b * 8 + SL) * PPAD + pp) << 5) + (ok & 31)] = v;
            } else {
                int ov = o - 512;
                *(float4*)&Vbuf[(((b * 4 + (ov >> 6)) * PPAD + pp) << 6) + (ov & 63)] = v;
            }
        }
    }
}

// ---------------------------------------------------------------------------
// Kernel 2: attention. One block per (b, g, output row i'). 384 threads.
// 8 lanes per output column j' (4-channel float4 slices).
// ---------------------------------------------------------------------------
__device__ __forceinline__ float red8(float v) {
    v += __shfl_xor_sync(0xffffffffu, v, 1);
    v += __shfl_xor_sync(0xffffffffu, v, 2);
    v += __shfl_xor_sync(0xffffffffu, v, 4);
    return v;
}
__device__ __forceinline__ float max8(float v) {
    v = fmaxf(v, __shfl_xor_sync(0xffffffffu, v, 1));
    v = fmaxf(v, __shfl_xor_sync(0xffffffffu, v, 2));
    v = fmaxf(v, __shfl_xor_sync(0xffffffffu, v, 4));
    return v;
}
__device__ __forceinline__ float dot4(float4 a, float4 b) {
    return a.x * b.x + a.y * b.y + a.z * b.z + a.w * b.w;
}

#define KT_F4 3456   // 8*54*32/4
#define VT_F4 6048   // 7*54*64/4
#define ATT_STRIDE 52

__global__ __launch_bounds__(384) void attn_kernel(const float* __restrict__ rpeh,
                                                   const float* __restrict__ rpew,
                                                   float* __restrict__ out) {
    extern __shared__ float sm[];
    float* Kt   = sm;                       // 13824 floats
    float* Vt   = sm + 13824;               // 24192 floats
    float* atts = Vt + 24192;               // 48*52 floats

    const int ip = blockIdx.x;   // output row i'
    const int g  = blockIdx.y;
    const int b  = blockIdx.z;
    const int t  = threadIdx.x;

    const int s_ = (ip >= 24) ? 1 : 0;
    const int SL = 2 * g + s_;
    const int R0 = 2 * ip - 48 * s_;

    // Stage K slab rows R0..R0+7 (contiguous) and V rows ip..ip+6 (contiguous)
    {
        const float4* ks = (const float4*)(Kbuf + (((b * 8 + SL) * PPAD + R0 * 54) << 5));
        float4* kt4 = (float4*)Kt;
        for (int i = t; i < KT_F4; i += 384) kt4[i] = ks[i];
        const float4* vsrc = (const float4*)(Vbuf + (((b * 4 + g) * PPAD + ip * 54) << 6));
        float4* vt4 = (float4*)Vt;
        for (int i = t; i < VT_F4; i += 384) vt4[i] = vsrc[i];
    }

    const int pos = t >> 3;   // j' 0..47
    const int sub = t & 7;    // lane within position

    // Load q slices (direct from gmem, coalesced)
    const float* qp = Qbuf + (((b * 4 + g) * 2304 + ip * 48 + pos) << 6);
    const float4 qlo = *(const float4*)(qp + 4 * sub);
    const float4 qhi = *(const float4*)(qp + 32 + 4 * sub);

    // RPE dot products: 7 values each for lo/hi halves
    const bool useH = (SL < 4);
    const float* rp = useH ? (rpeh + SL * 224) : (rpew + (SL - 4) * 224);
    float Rlo[7], Rhi[7];
#pragma unroll
    for (int tt = 0; tt < 7; tt++) {
        float4 rv = *(const float4*)(rp + tt * 32 + 4 * sub);
        Rlo[tt] = red8(dot4(qlo, rv));
        Rhi[tt] = red8(dot4(qhi, rv));
    }

    __syncthreads();

    const int rsel = (pos >= 24) ? 1 : 0;
    const int j0 = 2 * pos - 48 * rsel;   // even source column

    float Lreg[7] = {0.f, 0.f, 0.f, 0.f, 0.f, 0.f, 0.f};

    const float4* kt4 = (const float4*)Kt;
#pragma unroll
    for (int k = 0; k < 49; k++) {
        int wA, wB, rA, rB;
        if (k < 24)       { wA = 2 * k;      rA = 0; wB = 2 * k + 1;  rB = 0; }
        else if (k == 24) { wA = 48;         rA = 0; wB = 0;          rB = 1; }
        else              { wA = 2 * k - 49; rA = 1; wB = 2 * k - 48; rB = 1; }
        const int khA = wA / 7, kwA = wA % 7;
        const int khB = wB / 7, kwB = wB % 7;
        float4 va = kt4[(((rsel + khA) * 54 + j0 + rA + kwA) << 3) + sub];
        float4 vb = kt4[(((rsel + khB) * 54 + j0 + rB + kwB) << 3) + sub];
        float p = dot4(qlo, va) + dot4(qhi, vb);
        p = red8(p);
        float radd = useH ? (Rlo[khA] + Rhi[khB]) : (Rlo[kwA] + Rhi[kwB]);
        float L = p + radd;
        if ((k & 7) == sub) Lreg[k >> 3] = L;
    }

    // Softmax over 49, values distributed k = sub + 8*i across the 8 lanes
    const int nk = (sub == 0) ? 7 : 6;
    float m = -1e30f;
#pragma unroll
    for (int i = 0; i < 7; i++)
        if (i < nk) m = fmaxf(m, Lreg[i]);
    m = max8(m);
    float ssum = 0.f;
#pragma unroll
    for (int i = 0; i < 7; i++)
        if (i < nk) { Lreg[i] = __expf(Lreg[i] - m); ssum += Lreg[i]; }
    ssum = red8(ssum);
    float inv = 1.0f / ssum;
#pragma unroll
    for (int i = 0; i < 7; i++) {
        int k = sub + 8 * i;
        if (k < 49) atts[pos * ATT_STRIDE + k] = Lreg[i] * inv;
    }
    __syncwarp();

    // AV: lane accumulates channels {4sub..4sub+3} and {32+4sub..}
    float4 acc0 = make_float4(0.f, 0.f, 0.f, 0.f);
    float4 acc1 = make_float4(0.f, 0.f, 0.f, 0.f);
    const float4* vt4 = (const float4*)Vt;
#pragma unroll
    for (int k = 0; k < 49; k++) {
        const int kh = k / 7, kw = k % 7;
        float a = atts[pos * ATT_STRIDE + k];
        const float4* vv = vt4 + (((kh * 54 + pos + kw) << 4) + sub);
        float4 v0 = vv[0];
        float4 v1 = vv[8];
        acc0.x += a * v0.x; acc0.y += a * v0.y; acc0.z += a * v0.z; acc0.w += a * v0.w;
        acc1.x += a * v1.x; acc1.y += a * v1.y; acc1.z += a * v1.z; acc1.w += a * v1.w;
    }

    // Write out: out[b][g*64+c][ip][pos]
    float* op = out + (b * 256 + g * 64) * NPOS + ip * 48 + pos;
    op[(4 * sub + 0) * NPOS] = acc0.x;
    op[(4 * sub + 1) * NPOS] = acc0.y;
    op[(4 * sub + 2) * NPOS] = acc0.z;
    op[(4 * sub + 3) * NPOS] = acc0.w;
    op[(32 + 4 * sub + 0) * NPOS] = acc1.x;
    op[(32 + 4 * sub + 1) * NPOS] = acc1.y;
    op[(32 + 4 * sub + 2) * NPOS] = acc1.z;
    op[(32 + 4 * sub + 3) * NPOS] = acc1.w;
}

// ---------------------------------------------------------------------------
extern "C" void kernel_launch(void* const* d_in, const int* in_sizes, int n_in,
                              void* d_out, int out_size) {
    const float* x  = (const float*)d_in[0];
    const float* w  = (const float*)d_in[1];
    const float* rh = (const float*)d_in[2];
    const float* rw = (const float*)d_in[3];
    float* out = (float*)d_out;

    {
        const int items = 16 * 612 + 8 * 612;
        zero_border_kernel<<<(items + 255) / 256, 256>>>();
    }

    dim3 gc(18, 6, 2);   // n=2304/128, o=768/128, b
    conv_kernel<<<gc, 256>>>(x, w);

    const int SMEM = (13824 + 24192 + 48 * ATT_STRIDE) * 4;
    cudaFuncSetAttribute(attn_kernel, cudaFuncAttributeMaxDynamicSharedMemorySize, SMEM);
    dim3 ga(48, 4, 2);
    attn_kernel<<<ga, 384, SMEM>>>(rh, rw, out);
}

// round 4
// speedup vs baseline: 1.2337x; 1.2337x over previous
#include <cuda_runtime.h>

#define NPOS 2304          // 48*48
#define PPAD 2916          // 54*54
typedef unsigned long long ull;

// Scratch (device globals; no runtime allocation)
__device__ float Qbuf[2 * 4 * 2304 * 64];   // [b][g][p][c64]
__device__ float Kbuf[2 * 8 * 2916 * 32];   // [b][SL][padded pos][c32]  (borders never read)
__device__ float Vbuf[2 * 4 * 2916 * 64];   // [b][g][padded pos][c64]  (borders never read)

// ---------------------------------------------------------------------------
// f32x2 helpers
// ---------------------------------------------------------------------------
__device__ __forceinline__ ull dup2(float a) {
    ull r;
    asm("mov.b64 %0, {%1, %1};" : "=l"(r) : "f"(a));
    return r;
}
__device__ __forceinline__ void fma2(ull& d, ull a, ull b) {
    asm("fma.rn.f32x2 %0, %1, %2, %0;" : "+l"(d) : "l"(a), "l"(b));
}

// ---------------------------------------------------------------------------
// Kernel 1: 1x1 conv GEMM, FFMA2, conflict-free smem.
// C[768,2304] = W[768,256] * X[256,2304] per batch.
// Tile 128(o) x 64(n), 256 threads, microtile 8(o, packed in f32x2 pairs) x 4(n).
// ty = t&15 -> o (lane-fast, 16B stride LDS + coalesced STG), tx = t>>4 -> n.
// ---------------------------------------------------------------------------
__global__ __launch_bounds__(256, 3) void conv_kernel(const float* __restrict__ x,
                                                      const float* __restrict__ w) {
    __shared__ float As[16][128];   // [k][o]
    __shared__ float Bs[16][64];    // [k][n]

    const int b  = blockIdx.z;
    const int o0 = blockIdx.y * 128;
    const int n0 = blockIdx.x * 64;
    const int t  = threadIdx.x;
    const int ty = t & 15;      // o quad index
    const int tx = t >> 4;      // n quad index

    const float* Xb = x + b * (256 * NPOS);

    ull acc[4][4];              // [o-pair: q0p0,q0p1,q1p0,q1p1][n]
#pragma unroll
    for (int i = 0; i < 4; i++)
#pragma unroll
        for (int j = 0; j < 4; j++) acc[i][j] = 0ull;

    // A loader: 2048 floats/kstep, 2 float4/thread. fid = t + rep*256:
    //   ao = fid>>2 (0..127), akq = fid&3 (k quad) ; transposed scalar STS.
    // B loader: 1 float4/thread: bkk = t>>4, bn4 = t&15.
    for (int c0 = 0; c0 < 256; c0 += 16) {
        float4 av[2], bv;
#pragma unroll
        for (int rep = 0; rep < 2; rep++) {
            int fid = t + rep * 256;
            int ao = fid >> 2, akq = fid & 3;
            av[rep] = *(const float4*)(w + (o0 + ao) * 256 + c0 + akq * 4);
        }
        bv = *(const float4*)(Xb + (c0 + (t >> 4)) * NPOS + n0 + (t & 15) * 4);
        __syncthreads();
#pragma unroll
        for (int rep = 0; rep < 2; rep++) {
            int fid = t + rep * 256;
            int ao = fid >> 2, akq = fid & 3;
            As[akq * 4 + 0][ao] = av[rep].x;
            As[akq * 4 + 1][ao] = av[rep].y;
            As[akq * 4 + 2][ao] = av[rep].z;
            As[akq * 4 + 3][ao] = av[rep].w;
        }
        *(float4*)&Bs[t >> 4][(t & 15) * 4] = bv;
        __syncthreads();
#pragma unroll
        for (int kk = 0; kk < 16; kk++) {
            ull ap[4];
            *(float4*)(&ap[0]) = *(const float4*)&As[kk][ty * 4];        // o pairs (0,1),(2,3)
            *(float4*)(&ap[2]) = *(const float4*)&As[kk][64 + ty * 4];   // o pairs (64..)
            float bb[4];
            *(float4*)bb = *(const float4*)&Bs[kk][tx * 4];
            ull bd0 = dup2(bb[0]), bd1 = dup2(bb[1]), bd2 = dup2(bb[2]), bd3 = dup2(bb[3]);
#pragma unroll
            for (int op = 0; op < 4; op++) {
                fma2(acc[op][0], ap[op], bd0);
                fma2(acc[op][1], ap[op], bd1);
                fma2(acc[op][2], ap[op], bd2);
                fma2(acc[op][3], ap[op], bd3);
            }
        }
    }

    // Epilogue: no smem. Thread holds o = {o0+ty*4+0..3, o0+64+ty*4+0..3} for
    // n = n0+tx*4+0..3. Channel runs are contiguous -> STG.128, coalesced in ty.
#pragma unroll
    for (int nj = 0; nj < 4; nj++) {
        int hw = n0 + tx * 4 + nj;
        unsigned uhw = (unsigned)hw;
        int i2 = uhw / 48u, j2 = uhw - 48u * i2;
        int pp = (i2 + 3) * 54 + (j2 + 3);
#pragma unroll
        for (int half = 0; half < 2; half++) {
            float2 p0 = *(float2*)&acc[half * 2 + 0][nj];
            float2 p1 = *(float2*)&acc[half * 2 + 1][nj];
            float4 v = make_float4(p0.x, p0.y, p1.x, p1.y);
            int o = o0 + half * 64 + ty * 4;
            if (o < 256) {
                int g = o >> 6;
                *(float4*)&Qbuf[(((b * 4 + g) * 2304 + hw) << 6) + (o & 63)] = v;
            } else if (o < 512) {
                int ok = o - 256;
                int SL = ((ok >> 5) & 1) * 4 + (ok >> 6);
                *(float4*)&Kbuf[(((b * 8 + SL) * PPAD + pp) << 5) + (ok & 31)] = v;
            } else {
                int ov = o - 512;
                *(float4*)&Vbuf[(((b * 4 + (ov >> 6)) * PPAD + pp) << 6) + (ov & 63)] = v;
            }
        }
    }
}

// ---------------------------------------------------------------------------
// Kernel 2: attention. One block per (b, g, output row i'). 384 threads.
// Border positions are materialized as zeros during smem staging (Kbuf/Vbuf
// borders are never written by conv and never read here).
// ---------------------------------------------------------------------------
__device__ __forceinline__ float red8(float v) {
    v += __shfl_xor_sync(0xffffffffu, v, 1);
    v += __shfl_xor_sync(0xffffffffu, v, 2);
    v += __shfl_xor_sync(0xffffffffu, v, 4);
    return v;
}
__device__ __forceinline__ float max8(float v) {
    v = fmaxf(v, __shfl_xor_sync(0xffffffffu, v, 1));
    v = fmaxf(v, __shfl_xor_sync(0xffffffffu, v, 2));
    v = fmaxf(v, __shfl_xor_sync(0xffffffffu, v, 4));
    return v;
}
__device__ __forceinline__ float dot4(float4 a, float4 b) {
    return a.x * b.x + a.y * b.y + a.z * b.z + a.w * b.w;
}

#define KT_F4 3456   // 8*54*32/4
#define VT_F4 6048   // 7*54*64/4
#define ATT_STRIDE 52

__global__ __launch_bounds__(384) void attn_kernel(const float* __restrict__ rpeh,
                                                   const float* __restrict__ rpew,
                                                   float* __restrict__ out) {
    extern __shared__ float sm[];
    float* Kt   = sm;                       // 13824 floats
    float* Vt   = sm + 13824;               // 24192 floats
    float* atts = Vt + 24192;               // 48*52 floats

    const int ip = blockIdx.x;   // output row i'
    const int g  = blockIdx.y;
    const int b  = blockIdx.z;
    const int t  = threadIdx.x;

    const int s_ = (ip >= 24) ? 1 : 0;
    const int SL = 2 * g + s_;
    const int R0 = 2 * ip - 48 * s_;

    const float4 z4 = make_float4(0.f, 0.f, 0.f, 0.f);

    // Stage K slab rows R0..R0+7 and V rows ip..ip+6; zero-fill borders.
    {
        const float4* ks = (const float4*)(Kbuf + (((b * 8 + SL) * PPAD + R0 * 54) << 5));
        float4* kt4 = (float4*)Kt;
        for (int i = t; i < KT_F4; i += 384) {
            unsigned pl = (unsigned)(i >> 3);
            unsigned lr = pl / 54u, col = pl - 54u * lr;
            unsigned grow = (unsigned)R0 + lr;
            bool inter = (grow - 3u) < 48u && (col - 3u) < 48u;
            kt4[i] = inter ? ks[i] : z4;
        }
        const float4* vsrc = (const float4*)(Vbuf + (((b * 4 + g) * PPAD + ip * 54) << 6));
        float4* vt4 = (float4*)Vt;
        for (int i = t; i < VT_F4; i += 384) {
            unsigned pl = (unsigned)(i >> 4);
            unsigned lr = pl / 54u, col = pl - 54u * lr;
            unsigned grow = (unsigned)ip + lr;
            bool inter = (grow - 3u) < 48u && (col - 3u) < 48u;
            vt4[i] = inter ? vsrc[i] : z4;
        }
    }

    const int pos = t >> 3;   // j' 0..47
    const int sub = t & 7;    // lane within position

    const float* qp = Qbuf + (((b * 4 + g) * 2304 + ip * 48 + pos) << 6);
    const float4 qlo = *(const float4*)(qp + 4 * sub);
    const float4 qhi = *(const float4*)(qp + 32 + 4 * sub);

    // RPE dot products: 7 values each for lo/hi halves
    const bool useH = (SL < 4);
    const float* rp = useH ? (rpeh + SL * 224) : (rpew + (SL - 4) * 224);
    float Rlo[7], Rhi[7];
#pragma unroll
    for (int tt = 0; tt < 7; tt++) {
        float4 rv = *(const float4*)(rp + tt * 32 + 4 * sub);
        Rlo[tt] = red8(dot4(qlo, rv));
        Rhi[tt] = red8(dot4(qhi, rv));
    }

    __syncthreads();

    const int rsel = (pos >= 24) ? 1 : 0;
    const int j0 = 2 * pos - 48 * rsel;   // even source column

    float Lreg[7] = {0.f, 0.f, 0.f, 0.f, 0.f, 0.f, 0.f};

    const float4* kt4 = (const float4*)Kt;
#pragma unroll
    for (int k = 0; k < 49; k++) {
        int wA, wB, rA, rB;
        if (k < 24)       { wA = 2 * k;      rA = 0; wB = 2 * k + 1;  rB = 0; }
        else if (k == 24) { wA = 48;         rA = 0; wB = 0;          rB = 1; }
        else              { wA = 2 * k - 49; rA = 1; wB = 2 * k - 48; rB = 1; }
        const int khA = wA / 7, kwA = wA % 7;
        const int khB = wB / 7, kwB = wB % 7;
        float4 va = kt4[(((rsel + khA) * 54 + j0 + rA + kwA) << 3) + sub];
        float4 vb = kt4[(((rsel + khB) * 54 + j0 + rB + kwB) << 3) + sub];
        float p = dot4(qlo, va) + dot4(qhi, vb);
        p = red8(p);
        float radd = useH ? (Rlo[khA] + Rhi[khB]) : (Rlo[kwA] + Rhi[kwB]);
        float L = p + radd;
        if ((k & 7) == sub) Lreg[k >> 3] = L;
    }

    // Softmax over 49, values distributed k = sub + 8*i across the 8 lanes
    const int nk = (sub == 0) ? 7 : 6;
    float m = -1e30f;
#pragma unroll
    for (int i = 0; i < 7; i++)
        if (i < nk) m = fmaxf(m, Lreg[i]);
    m = max8(m);
    float ssum = 0.f;
#pragma unroll
    for (int i = 0; i < 7; i++)
        if (i < nk) { Lreg[i] = __expf(Lreg[i] - m); ssum += Lreg[i]; }
    ssum = red8(ssum);
    float inv = 1.0f / ssum;
#pragma unroll
    for (int i = 0; i < 7; i++) {
        int k = sub + 8 * i;
        if (k < 49) atts[pos * ATT_STRIDE + k] = Lreg[i] * inv;
    }
    __syncwarp();

    // AV: lane accumulates channels {4sub..4sub+3} and {32+4sub..}
    float4 acc0 = make_float4(0.f, 0.f, 0.f, 0.f);
    float4 acc1 = make_float4(0.f, 0.f, 0.f, 0.f);
    const float4* vt4 = (const float4*)Vt;
#pragma unroll
    for (int k = 0; k < 49; k++) {
        const int kh = k / 7, kw = k % 7;
        float a = atts[pos * ATT_STRIDE + k];
        const float4* vv = vt4 + (((kh * 54 + pos + kw) << 4) + sub);
        float4 v0 = vv[0];
        float4 v1 = vv[8];
        acc0.x += a * v0.x; acc0.y += a * v0.y; acc0.z += a * v0.z; acc0.w += a * v0.w;
        acc1.x += a * v1.x; acc1.y += a * v1.y; acc1.z += a * v1.z; acc1.w += a * v1.w;
    }

    // Write out: out[b][g*64+c][ip][pos]
    float* op = out + (b * 256 + g * 64) * NPOS + ip * 48 + pos;
    op[(4 * sub + 0) * NPOS] = acc0.x;
    op[(4 * sub + 1) * NPOS] = acc0.y;
    op[(4 * sub + 2) * NPOS] = acc0.z;
    op[(4 * sub + 3) * NPOS] = acc0.w;
    op[(32 + 4 * sub + 0) * NPOS] = acc1.x;
    op[(32 + 4 * sub + 1) * NPOS] = acc1.y;
    op[(32 + 4 * sub + 2) * NPOS] = acc1.z;
    op[(32 + 4 * sub + 3) * NPOS] = acc1.w;
}

// ---------------------------------------------------------------------------
extern "C" void kernel_launch(void* const* d_in, const int* in_sizes, int n_in,
                              void* d_out, int out_size) {
    const float* x  = (const float*)d_in[0];
    const float* w  = (const float*)d_in[1];
    const float* rh = (const float*)d_in[2];
    const float* rw = (const float*)d_in[3];
    float* out = (float*)d_out;

    dim3 gc(36, 6, 2);   // n=2304/64, o=768/128, b
    conv_kernel<<<gc, 256>>>(x, w);

    const int SMEM = (13824 + 24192 + 48 * ATT_STRIDE) * 4;
    cudaFuncSetAttribute(attn_kernel, cudaFuncAttributeMaxDynamicSharedMemorySize, SMEM);
    dim3 ga(48, 4, 2);
    attn_kernel<<<ga, 384, SMEM>>>(rh, rw, out);
}